// round 13
// baseline (speedup 1.0000x reference)
#include <cuda_runtime.h>
#include <cuda_fp16.h>
#include <cstdint>

// ---------------------------------------------------------------------------
// Problem dims
// ---------------------------------------------------------------------------
#define HID   2048
#define CH    4096
#define SEQ   4096
#define BATCH 4
#define MROWS (BATCH * SEQ)   // 16384

// ---------------------------------------------------------------------------
// Device scratch (allocation-free rule)
// ---------------------------------------------------------------------------
__device__ __half g_hs16  [(size_t)MROWS * HID];   // hs as fp16
__device__ __half g_win16 [(size_t)CH * HID];      // w_in as fp16
__device__ __half g_wout16[(size_t)HID * CH];      // w_out as fp16
__device__ __half g_x     [(size_t)MROWS * CH];    // after in-proj (fp16)
__device__ __half g_y     [(size_t)MROWS * CH];    // conv+silu (fp16)

// ---------------------------------------------------------------------------
// PTX helpers (arch-generic: cp.async / ldmatrix / mma.sync)
// ---------------------------------------------------------------------------
__device__ __forceinline__ uint32_t smem_u32(const void* p) {
    uint32_t a;
    asm("{ .reg .u64 t; cvta.to.shared.u64 t, %1; cvt.u32.u64 %0, t; }" : "=r"(a) : "l"(p));
    return a;
}
__device__ __forceinline__ void cp16(uint32_t dst, const void* src) {
    asm volatile("cp.async.cg.shared.global [%0], [%1], 16;" :: "r"(dst), "l"(src));
}
__device__ __forceinline__ void cp_commit() { asm volatile("cp.async.commit_group;" ::: "memory"); }
__device__ __forceinline__ void cp_wait2()  { asm volatile("cp.async.wait_group 2;"  ::: "memory"); }
__device__ __forceinline__ void cp_wait0()  { asm volatile("cp.async.wait_group 0;"  ::: "memory"); }

__device__ __forceinline__ void ldsm_x4(uint32_t* r, uint32_t addr) {
    asm volatile("ldmatrix.sync.aligned.m8n8.x4.shared.b16 {%0,%1,%2,%3}, [%4];"
        : "=r"(r[0]), "=r"(r[1]), "=r"(r[2]), "=r"(r[3]) : "r"(addr));
}
__device__ __forceinline__ void mma16816(float* c, const uint32_t* a, const uint32_t* b) {
    asm volatile(
        "mma.sync.aligned.m16n8k16.row.col.f32.f16.f16.f32 "
        "{%0,%1,%2,%3}, {%4,%5,%6,%7}, {%8,%9}, {%0,%1,%2,%3};"
        : "+f"(c[0]), "+f"(c[1]), "+f"(c[2]), "+f"(c[3])
        : "r"(a[0]), "r"(a[1]), "r"(a[2]), "r"(a[3]), "r"(b[0]), "r"(b[1]));
}

// ---------------------------------------------------------------------------
// GEMM: C[m,n] = sum_k A[m,k]*B[n,k] + bias[n]   (fp16 in, fp32 acc)
// CTA 128x128, 8 warps (warp tile 32x64), BK=64, 3 stages, occ 2.
// LDA=72 (144B rows) -> conflict-free ldsm.
// R9/R11-proven schedule: ldsm(kk0) FIRST after the barrier, then load_A
// after kk0 and load_B after kk1.  DO NOT REORDER (R7/R10 regressions).
// This round: address-math shave only — no modulo, hoisted 64-bit pointer
// bases, accumulator-style k offsets.  Memory-op order unchanged.
// ---------------------------------------------------------------------------
#define BK    64
#define LDA   72
#define MATB  (128 * LDA)                 // 9216 elems / tile
#define STAGE_ELEMS (2 * MATB)            // A, B
#define STAGES 3
#define STAGE_BYTES (STAGE_ELEMS * 2)
#define GEMM_SMEM (STAGES * STAGE_BYTES)  // 110592 bytes

template <typename OutT>
__global__ void __launch_bounds__(256, 2)
gemm_fp16(const __half* __restrict__ A, const __half* __restrict__ B,
          const float* __restrict__ bias, OutT* __restrict__ C,
          int M, int N, int K)
{
    extern __shared__ __align__(16) char smraw[];
    const uint32_t sbase = smem_u32(smraw);

    const int tid  = threadIdx.x;
    const int wid  = tid >> 5;
    const int lane = tid & 31;
    const int bm   = blockIdx.y * 128;
    const int bn   = blockIdx.x * 128;
    const int wm   = (wid & 3) * 32;     // warp row offset
    const int wn   = (wid >> 2) * 64;    // warp col offset

    // precomputed per-warp ldsm byte offsets (vary only by +kk*32 in-loop)
    uint32_t aBase[2], bBase[4];
#pragma unroll
    for (int mt = 0; mt < 2; mt++)
        aBase[mt] = (uint32_t)((wm + mt * 16 + (lane & 15)) * LDA + (lane >> 4) * 8) * 2;
#pragma unroll
    for (int q = 0; q < 4; q++)
        bBase[q] = (uint32_t)((wn + q * 16 + (lane & 7) + ((lane >> 4) << 3)) * LDA
                              + ((lane >> 3) & 1) * 8) * 2;

    // loader: hoisted global bases (per-thread, loop-invariant)
    const int lrow = tid >> 3;
    const int lkc  = (tid & 7) * 8;
    const uint32_t lsoff = (uint32_t)(lrow * LDA + lkc) * 2;
    const __half* Aptr = A + (size_t)(bm + lrow) * K + lkc;
    const __half* Bptr = B + (size_t)(bn + lrow) * K + lkc;

    float acc[2][8][4];
#pragma unroll
    for (int i = 0; i < 2; i++)
#pragma unroll
        for (int j = 0; j < 8; j++)
#pragma unroll
            for (int k = 0; k < 4; k++) acc[i][j][k] = 0.0f;

    const int nchunks = K / BK;

    // half-stage loaders: one 64-bit add per cp16 (i*32*K folds to constant)
    auto load_A = [&](uint32_t stA, int k0) {
#pragma unroll
        for (int i = 0; i < 4; i++)
            cp16(stA + lsoff + (uint32_t)(32 * i) * (LDA * 2),
                 Aptr + k0 + (size_t)(32 * i) * K);
        cp_commit();
    };
    auto load_B = [&](uint32_t stB, int k0) {
#pragma unroll
        for (int i = 0; i < 4; i++)
            cp16(stB + lsoff + (uint32_t)(32 * i) * (LDA * 2),
                 Bptr + k0 + (size_t)(32 * i) * K);
        cp_commit();
    };

    auto do_kk = [&](uint32_t sA, uint32_t sB, int kk) {
        const uint32_t ko = (uint32_t)kk * 32;
        uint32_t a[2][4];
#pragma unroll
        for (int mt = 0; mt < 2; mt++) ldsm_x4(a[mt], sA + aBase[mt] + ko);
        uint32_t b[4][4];
#pragma unroll
        for (int q = 0; q < 4; q++)    ldsm_x4(b[q], sB + bBase[q] + ko);
#pragma unroll
        for (int mt = 0; mt < 2; mt++)
#pragma unroll
            for (int q = 0; q < 4; q++)
#pragma unroll
                for (int h = 0; h < 2; h++)
                    mma16816(acc[mt][q * 2 + h], a[mt], &b[q][h * 2]);
    };

    // prologue: 2 stages in flight (4 commit groups)
    load_A(sbase, 0);
    load_B(sbase + MATB * 2, 0);
    load_A(sbase + STAGE_BYTES, BK);
    load_B(sbase + STAGE_BYTES + MATB * 2, BK);

    int slot = 0, pslot = 2, pk = 2 * BK;
    for (int i = 0; i < nchunks; i++) {
        if (i + 1 < nchunks) cp_wait2(); else cp_wait0();
        __syncthreads();

        const uint32_t sA = sbase + (uint32_t)slot * STAGE_BYTES;
        const uint32_t sB = sA + MATB * 2;
        const uint32_t pA = sbase + (uint32_t)pslot * STAGE_BYTES;
        const bool pf = (i + 2 < nchunks);

        do_kk(sA, sB, 0);
        if (pf) load_A(pA, pk);
        do_kk(sA, sB, 1);
        if (pf) load_B(pA + MATB * 2, pk);
        do_kk(sA, sB, 2);
        do_kk(sA, sB, 3);
        // single barrier per iteration: slot (i+2)%3 was last read in iter
        // i-1, ordered by this iteration's __syncthreads.

        if (++slot == STAGES) slot = 0;
        if (++pslot == STAGES) pslot = 0;
        pk += BK;
    }

    // --- epilogue: fused bias ---
    const int r  = lane >> 2;
    const int cc = (lane & 3) * 2;
#pragma unroll
    for (int mt = 0; mt < 2; mt++) {
        const int row0 = bm + wm + mt * 16;
#pragma unroll
        for (int nt = 0; nt < 8; nt++) {
            const int col0 = bn + wn + nt * 8;
            const float2 bv = *reinterpret_cast<const float2*>(bias + col0 + cc);
            const float v00 = acc[mt][nt][0] + bv.x, v01 = acc[mt][nt][1] + bv.y;
            const float v10 = acc[mt][nt][2] + bv.x, v11 = acc[mt][nt][3] + bv.y;
            OutT* p0 = C + (size_t)(row0 + r) * N + col0 + cc;
            OutT* p1 = C + (size_t)(row0 + r + 8) * N + col0 + cc;
            if constexpr (sizeof(OutT) == 4) {
                float2 o0, o1;
                o0.x = v00; o0.y = v01; o1.x = v10; o1.y = v11;
                *reinterpret_cast<float2*>(p0) = o0;
                *reinterpret_cast<float2*>(p1) = o1;
            } else {
                __half2 o0, o1;
                o0.x = __float2half(v00); o0.y = __float2half(v01);
                o1.x = __float2half(v10); o1.y = __float2half(v11);
                *reinterpret_cast<__half2*>(p0) = o0;
                *reinterpret_cast<__half2*>(p1) = o1;
            }
        }
    }
}

// ---------------------------------------------------------------------------
// Fused fp32 -> fp16 convert over THREE arrays in one launch (grid-stride).
// ---------------------------------------------------------------------------
__global__ void __launch_bounds__(256)
convert_fp16_fused(const float* __restrict__ s0, __half* __restrict__ d0, long long n0,
                   const float* __restrict__ s1, __half* __restrict__ d1, long long n1,
                   const float* __restrict__ s2, __half* __restrict__ d2, long long n2)
{
    const long long total = n0 + n1 + n2;
    const long long stride = (long long)gridDim.x * blockDim.x;
    for (long long i = (long long)blockIdx.x * blockDim.x + threadIdx.x;
         i < total; i += stride) {
        const float* src; __half* dst; long long j;
        if (i < n0)           { src = s0; dst = d0; j = i; }
        else if (i < n0 + n1) { src = s1; dst = d1; j = i - n0; }
        else                  { src = s2; dst = d2; j = i - n0 - n1; }
        const float4 v = reinterpret_cast<const float4*>(src)[j];
        __half2 p0, p1;
        p0.x = __float2half(v.x); p0.y = __float2half(v.y);
        p1.x = __float2half(v.z); p1.y = __float2half(v.w);
        reinterpret_cast<__half2*>(dst)[2 * j]     = p0;
        reinterpret_cast<__half2*>(dst)[2 * j + 1] = p1;
    }
}

// ---------------------------------------------------------------------------
// Causal depthwise conv (K=4) + bias + SiLU, fp16 in -> fp16 out.
// Each thread handles TWO adjacent channels (half2) x SCH seq positions.
// ---------------------------------------------------------------------------
#define SCH 64
__global__ void __launch_bounds__(256)
conv_silu(const __half* __restrict__ x, const float* __restrict__ cw,
          const float* __restrict__ cb, __half* __restrict__ y)
{
    const int c2 = blockIdx.x * 256 + threadIdx.x;   // half2 channel index
    const int c  = c2 * 2;
    const int b  = blockIdx.z;
    const int s0 = blockIdx.y * SCH;

    const float4 wA = *reinterpret_cast<const float4*>(cw + (size_t)c * 4);
    const float4 wB = *reinterpret_cast<const float4*>(cw + (size_t)(c + 1) * 4);
    const float2 bias = *reinterpret_cast<const float2*>(cb + c);

    const __half2* xp = reinterpret_cast<const __half2*>(x) + c2;
    __half2*       yp = reinterpret_cast<__half2*>(y) + c2;
    const size_t CH2 = CH / 2;
    const size_t base = (size_t)b * SEQ * CH2;

    float2 m3, m2, m1;
    if (s0 == 0) { m3 = m2 = m1 = make_float2(0.f, 0.f); }
    else {
        m3 = __half22float2(xp[base + (size_t)(s0 - 3) * CH2]);
        m2 = __half22float2(xp[base + (size_t)(s0 - 2) * CH2]);
        m1 = __half22float2(xp[base + (size_t)(s0 - 1) * CH2]);
    }

#pragma unroll 4
    for (int s = s0; s < s0 + SCH; s++) {
        const float2 xc = __half22float2(xp[base + (size_t)s * CH2]);
        float a0 = bias.x, a1 = bias.y;
        a0 = fmaf(wA.x, m3.x, a0);  a1 = fmaf(wB.x, m3.y, a1);
        a0 = fmaf(wA.y, m2.x, a0);  a1 = fmaf(wB.y, m2.y, a1);
        a0 = fmaf(wA.z, m1.x, a0);  a1 = fmaf(wB.z, m1.y, a1);
        a0 = fmaf(wA.w, xc.x, a0);  a1 = fmaf(wB.w, xc.y, a1);
        const float v0 = a0 / (1.0f + __expf(-a0));
        const float v1 = a1 / (1.0f + __expf(-a1));
        __half2 o;
        o.x = __float2half(v0);
        o.y = __float2half(v1);
        yp[base + (size_t)s * CH2] = o;
        m3 = m2; m2 = m1; m1 = xc;
    }
}

// ---------------------------------------------------------------------------
// Launch: hidden_states, w_in, b_in, conv_w, conv_b, w_out, b_out
// ---------------------------------------------------------------------------
extern "C" void kernel_launch(void* const* d_in, const int* in_sizes, int n_in,
                              void* d_out, int out_size)
{
    const float* hs     = (const float*)d_in[0];
    const float* w_in   = (const float*)d_in[1];
    const float* b_in   = (const float*)d_in[2];
    const float* conv_w = (const float*)d_in[3];
    const float* conv_b = (const float*)d_in[4];
    const float* w_out  = (const float*)d_in[5];
    const float* b_out  = (const float*)d_in[6];
    float* out = (float*)d_out;

    __half *hs16, *win16, *wout16, *xbuf, *ybuf;
    cudaGetSymbolAddress((void**)&hs16,   g_hs16);
    cudaGetSymbolAddress((void**)&win16,  g_win16);
    cudaGetSymbolAddress((void**)&wout16, g_wout16);
    cudaGetSymbolAddress((void**)&xbuf,   g_x);
    cudaGetSymbolAddress((void**)&ybuf,   g_y);

    cudaFuncSetAttribute(gemm_fp16<__half>, cudaFuncAttributeMaxDynamicSharedMemorySize, GEMM_SMEM);
    cudaFuncSetAttribute(gemm_fp16<float>,  cudaFuncAttributeMaxDynamicSharedMemorySize, GEMM_SMEM);

    // fused fp16 conversions (one launch for hs, w_in, w_out)
    {
        const long long n0 = (long long)MROWS * HID / 4;   // hs
        const long long n1 = (long long)CH * HID / 4;      // w_in
        const long long n2 = (long long)HID * CH / 4;      // w_out
        convert_fp16_fused<<<2368, 256>>>(hs, hs16, n0,
                                          w_in, win16, n1,
                                          w_out, wout16, n2);
    }

    // GEMM1: x = hs @ w_in^T + b_in   [16384, 4096]  (fp16 out)
    {
        dim3 grid(CH / 128, MROWS / 128);   // (32, 128)
        gemm_fp16<__half><<<grid, 256, GEMM_SMEM>>>(hs16, win16, b_in, xbuf,
                                                    MROWS, CH, HID);
    }

    // conv + SiLU -> y (fp16), 2 channels per thread
    {
        dim3 grid((CH / 2) / 256, SEQ / SCH, BATCH);  // (8, 64, 4)
        conv_silu<<<grid, 256>>>(xbuf, conv_w, conv_b, ybuf);
    }

    // GEMM2: out = y @ w_out^T + b_out  [16384, 2048]  (fp32 out)
    {
        dim3 grid(HID / 128, MROWS / 128);  // (16, 128)
        gemm_fp16<float><<<grid, 256, GEMM_SMEM>>>(ybuf, wout16, b_out, out,
                                                   MROWS, HID, CH);
    }
}

// round 14
// speedup vs baseline: 1.0231x; 1.0231x over previous
#include <cuda_runtime.h>
#include <cuda_fp16.h>
#include <cstdint>

// ---------------------------------------------------------------------------
// Problem dims
// ---------------------------------------------------------------------------
#define HID   2048
#define CH    4096
#define SEQ   4096
#define BATCH 4
#define MROWS (BATCH * SEQ)   // 16384

// ---------------------------------------------------------------------------
// Device scratch (allocation-free rule)
// ---------------------------------------------------------------------------
__device__ __half g_hs16  [(size_t)MROWS * HID];   // hs as fp16
__device__ __half g_win16 [(size_t)CH * HID];      // w_in as fp16
__device__ __half g_wout16[(size_t)HID * CH];      // w_out as fp16
__device__ __half g_x     [(size_t)MROWS * CH];    // after in-proj (fp16)
__device__ __half g_y     [(size_t)MROWS * CH];    // conv+silu (fp16)

// ---------------------------------------------------------------------------
// PTX helpers (arch-generic: cp.async / ldmatrix / mma.sync)
// ---------------------------------------------------------------------------
__device__ __forceinline__ uint32_t smem_u32(const void* p) {
    uint32_t a;
    asm("{ .reg .u64 t; cvta.to.shared.u64 t, %1; cvt.u32.u64 %0, t; }" : "=r"(a) : "l"(p));
    return a;
}
__device__ __forceinline__ void cp16(uint32_t dst, const void* src) {
    asm volatile("cp.async.cg.shared.global [%0], [%1], 16;" :: "r"(dst), "l"(src));
}
__device__ __forceinline__ void cp_commit() { asm volatile("cp.async.commit_group;" ::: "memory"); }
__device__ __forceinline__ void cp_wait2()  { asm volatile("cp.async.wait_group 2;"  ::: "memory"); }
__device__ __forceinline__ void cp_wait0()  { asm volatile("cp.async.wait_group 0;"  ::: "memory"); }

__device__ __forceinline__ void ldsm_x4(uint32_t* r, uint32_t addr) {
    asm volatile("ldmatrix.sync.aligned.m8n8.x4.shared.b16 {%0,%1,%2,%3}, [%4];"
        : "=r"(r[0]), "=r"(r[1]), "=r"(r[2]), "=r"(r[3]) : "r"(addr));
}
__device__ __forceinline__ void mma16816(float* c, const uint32_t* a, const uint32_t* b) {
    asm volatile(
        "mma.sync.aligned.m16n8k16.row.col.f32.f16.f16.f32 "
        "{%0,%1,%2,%3}, {%4,%5,%6,%7}, {%8,%9}, {%0,%1,%2,%3};"
        : "+f"(c[0]), "+f"(c[1]), "+f"(c[2]), "+f"(c[3])
        : "r"(a[0]), "r"(a[1]), "r"(a[2]), "r"(a[3]), "r"(b[0]), "r"(b[1]));
}

// ---------------------------------------------------------------------------
// GEMM: C[m,n] = sum_k A[m,k]*B[n,k] + bias[n]   (fp16 in, fp32 acc)
// CTA 128x128, 8 warps (warp tile 32x64), BK=64, 3 stages, occ 2.
// LDA=72 (144B rows) -> conflict-free ldsm.
// R12-FROZEN SOURCE: this exact formulation measured 588us/GEMM, 77.8%
// tensor.  Three perturbations (R7, R10, R13) all regressed it.
// DO NOT REORDER OR REWRITE ADDRESS MATH.
// ---------------------------------------------------------------------------
#define BK    64
#define LDA   72
#define MATB  (128 * LDA)                 // 9216 elems / tile
#define STAGE_ELEMS (2 * MATB)            // A, B
#define STAGES 3
#define GEMM_SMEM (STAGES * STAGE_ELEMS * 2)  // 110592 bytes

template <typename OutT>
__global__ void __launch_bounds__(256, 2)
gemm_fp16(const __half* __restrict__ A, const __half* __restrict__ B,
          const float* __restrict__ bias, OutT* __restrict__ C,
          int M, int N, int K)
{
    extern __shared__ __align__(16) char smraw[];
    const uint32_t sbase = smem_u32(smraw);

    const int tid  = threadIdx.x;
    const int wid  = tid >> 5;
    const int lane = tid & 31;
    const int bm   = blockIdx.y * 128;
    const int bn   = blockIdx.x * 128;
    const int wm   = (wid & 3) * 32;     // warp row offset
    const int wn   = (wid >> 2) * 64;    // warp col offset

    // precomputed per-warp ldsm byte offsets (vary only by +kk*32 in-loop)
    uint32_t aBase[2], bBase[4];
#pragma unroll
    for (int mt = 0; mt < 2; mt++)
        aBase[mt] = (uint32_t)((wm + mt * 16 + (lane & 15)) * LDA + (lane >> 4) * 8) * 2;
#pragma unroll
    for (int q = 0; q < 4; q++)
        bBase[q] = (uint32_t)((wn + q * 16 + (lane & 7) + ((lane >> 4) << 3)) * LDA
                              + ((lane >> 3) & 1) * 8) * 2;

    // loader offsets
    const int lrow = tid >> 3;
    const int lkc  = (tid & 7) * 8;
    const uint32_t lsoff = (uint32_t)(lrow * LDA + lkc) * 2;

    float acc[2][8][4];
#pragma unroll
    for (int i = 0; i < 2; i++)
#pragma unroll
        for (int j = 0; j < 8; j++)
#pragma unroll
            for (int k = 0; k < 4; k++) acc[i][j][k] = 0.0f;

    const int nchunks = K / BK;

    // half-stage loaders (A half / B half), each its own commit group
    auto load_A = [&](int slot, int k0) {
        const uint32_t st = sbase + (uint32_t)slot * STAGE_ELEMS * 2;
#pragma unroll
        for (int i = 0; i < 4; i++)
            cp16(st + lsoff + (uint32_t)(32 * i) * LDA * 2,
                 A + (size_t)(bm + lrow + 32 * i) * K + k0 + lkc);
        cp_commit();
    };
    auto load_B = [&](int slot, int k0) {
        const uint32_t st = sbase + (uint32_t)slot * STAGE_ELEMS * 2 + MATB * 2;
#pragma unroll
        for (int i = 0; i < 4; i++)
            cp16(st + lsoff + (uint32_t)(32 * i) * LDA * 2,
                 B + (size_t)(bn + lrow + 32 * i) * K + k0 + lkc);
        cp_commit();
    };

    auto do_kk = [&](uint32_t sA, uint32_t sB, int kk) {
        const uint32_t ko = (uint32_t)kk * 32;
        uint32_t a[2][4];
#pragma unroll
        for (int mt = 0; mt < 2; mt++) ldsm_x4(a[mt], sA + aBase[mt] + ko);
        uint32_t b[4][4];
#pragma unroll
        for (int q = 0; q < 4; q++)    ldsm_x4(b[q], sB + bBase[q] + ko);
#pragma unroll
        for (int mt = 0; mt < 2; mt++)
#pragma unroll
            for (int q = 0; q < 4; q++)
#pragma unroll
                for (int h = 0; h < 2; h++)
                    mma16816(acc[mt][q * 2 + h], a[mt], &b[q][h * 2]);
    };

    // prologue: 2 stages in flight (4 commit groups)
    load_A(0, 0);      load_B(0, 0);
    load_A(1, BK);     load_B(1, BK);

    for (int i = 0; i < nchunks; i++) {
        if (i + 1 < nchunks) cp_wait2(); else cp_wait0();
        __syncthreads();

        const uint32_t st = sbase + (uint32_t)(i % STAGES) * STAGE_ELEMS * 2;
        const uint32_t sA = st;
        const uint32_t sB = st + MATB * 2;
        const bool pf = (i + 2 < nchunks);
        const int  ps = (i + 2) % STAGES;
        const int  pk = (i + 2) * BK;

        do_kk(sA, sB, 0);
        if (pf) load_A(ps, pk);
        do_kk(sA, sB, 1);
        if (pf) load_B(ps, pk);
        do_kk(sA, sB, 2);
        do_kk(sA, sB, 3);
        // single barrier per iteration: slot (i+2)%3 was last read in iter
        // i-1, ordered by this iteration's __syncthreads.
    }

    // --- epilogue: fused bias ---
    const int r  = lane >> 2;
    const int cc = (lane & 3) * 2;
#pragma unroll
    for (int mt = 0; mt < 2; mt++) {
        const int row0 = bm + wm + mt * 16;
#pragma unroll
        for (int nt = 0; nt < 8; nt++) {
            const int col0 = bn + wn + nt * 8;
            const float2 bv = *reinterpret_cast<const float2*>(bias + col0 + cc);
            const float v00 = acc[mt][nt][0] + bv.x, v01 = acc[mt][nt][1] + bv.y;
            const float v10 = acc[mt][nt][2] + bv.x, v11 = acc[mt][nt][3] + bv.y;
            OutT* p0 = C + (size_t)(row0 + r) * N + col0 + cc;
            OutT* p1 = C + (size_t)(row0 + r + 8) * N + col0 + cc;
            if constexpr (sizeof(OutT) == 4) {
                float2 o0, o1;
                o0.x = v00; o0.y = v01; o1.x = v10; o1.y = v11;
                *reinterpret_cast<float2*>(p0) = o0;
                *reinterpret_cast<float2*>(p1) = o1;
            } else {
                __half2 o0, o1;
                o0.x = __float2half(v00); o0.y = __float2half(v01);
                o1.x = __float2half(v10); o1.y = __float2half(v11);
                *reinterpret_cast<__half2*>(p0) = o0;
                *reinterpret_cast<__half2*>(p1) = o1;
            }
        }
    }
}

// ---------------------------------------------------------------------------
// Fused fp32 -> fp16 convert over THREE arrays in one launch (grid-stride).
// ---------------------------------------------------------------------------
__global__ void __launch_bounds__(256)
convert_fp16_fused(const float* __restrict__ s0, __half* __restrict__ d0, long long n0,
                   const float* __restrict__ s1, __half* __restrict__ d1, long long n1,
                   const float* __restrict__ s2, __half* __restrict__ d2, long long n2)
{
    const long long total = n0 + n1 + n2;
    const long long stride = (long long)gridDim.x * blockDim.x;
    for (long long i = (long long)blockIdx.x * blockDim.x + threadIdx.x;
         i < total; i += stride) {
        const float* src; __half* dst; long long j;
        if (i < n0)           { src = s0; dst = d0; j = i; }
        else if (i < n0 + n1) { src = s1; dst = d1; j = i - n0; }
        else                  { src = s2; dst = d2; j = i - n0 - n1; }
        const float4 v = reinterpret_cast<const float4*>(src)[j];
        __half2 p0, p1;
        p0.x = __float2half(v.x); p0.y = __float2half(v.y);
        p1.x = __float2half(v.z); p1.y = __float2half(v.w);
        reinterpret_cast<__half2*>(dst)[2 * j]     = p0;
        reinterpret_cast<__half2*>(dst)[2 * j + 1] = p1;
    }
}

// ---------------------------------------------------------------------------
// Causal depthwise conv (K=4) + bias + SiLU, fp16 in -> fp16 out.
// Each thread handles TWO adjacent channels (half2) x SCH seq positions.
// ---------------------------------------------------------------------------
#define SCH 64
__global__ void __launch_bounds__(256)
conv_silu(const __half* __restrict__ x, const float* __restrict__ cw,
          const float* __restrict__ cb, __half* __restrict__ y)
{
    const int c2 = blockIdx.x * 256 + threadIdx.x;   // half2 channel index
    const int c  = c2 * 2;
    const int b  = blockIdx.z;
    const int s0 = blockIdx.y * SCH;

    const float4 wA = *reinterpret_cast<const float4*>(cw + (size_t)c * 4);
    const float4 wB = *reinterpret_cast<const float4*>(cw + (size_t)(c + 1) * 4);
    const float2 bias = *reinterpret_cast<const float2*>(cb + c);

    const __half2* xp = reinterpret_cast<const __half2*>(x) + c2;
    __half2*       yp = reinterpret_cast<__half2*>(y) + c2;
    const size_t CH2 = CH / 2;
    const size_t base = (size_t)b * SEQ * CH2;

    float2 m3, m2, m1;
    if (s0 == 0) { m3 = m2 = m1 = make_float2(0.f, 0.f); }
    else {
        m3 = __half22float2(xp[base + (size_t)(s0 - 3) * CH2]);
        m2 = __half22float2(xp[base + (size_t)(s0 - 2) * CH2]);
        m1 = __half22float2(xp[base + (size_t)(s0 - 1) * CH2]);
    }

#pragma unroll 8
    for (int s = s0; s < s0 + SCH; s++) {
        const float2 xc = __half22float2(xp[base + (size_t)s * CH2]);
        float a0 = bias.x, a1 = bias.y;
        a0 = fmaf(wA.x, m3.x, a0);  a1 = fmaf(wB.x, m3.y, a1);
        a0 = fmaf(wA.y, m2.x, a0);  a1 = fmaf(wB.y, m2.y, a1);
        a0 = fmaf(wA.z, m1.x, a0);  a1 = fmaf(wB.z, m1.y, a1);
        a0 = fmaf(wA.w, xc.x, a0);  a1 = fmaf(wB.w, xc.y, a1);
        const float v0 = a0 / (1.0f + __expf(-a0));
        const float v1 = a1 / (1.0f + __expf(-a1));
        __half2 o;
        o.x = __float2half(v0);
        o.y = __float2half(v1);
        yp[base + (size_t)s * CH2] = o;
        m3 = m2; m2 = m1; m1 = xc;
    }
}

// ---------------------------------------------------------------------------
// Launch: hidden_states, w_in, b_in, conv_w, conv_b, w_out, b_out
// ---------------------------------------------------------------------------
extern "C" void kernel_launch(void* const* d_in, const int* in_sizes, int n_in,
                              void* d_out, int out_size)
{
    const float* hs     = (const float*)d_in[0];
    const float* w_in   = (const float*)d_in[1];
    const float* b_in   = (const float*)d_in[2];
    const float* conv_w = (const float*)d_in[3];
    const float* conv_b = (const float*)d_in[4];
    const float* w_out  = (const float*)d_in[5];
    const float* b_out  = (const float*)d_in[6];
    float* out = (float*)d_out;

    __half *hs16, *win16, *wout16, *xbuf, *ybuf;
    cudaGetSymbolAddress((void**)&hs16,   g_hs16);
    cudaGetSymbolAddress((void**)&win16,  g_win16);
    cudaGetSymbolAddress((void**)&wout16, g_wout16);
    cudaGetSymbolAddress((void**)&xbuf,   g_x);
    cudaGetSymbolAddress((void**)&ybuf,   g_y);

    cudaFuncSetAttribute(gemm_fp16<__half>, cudaFuncAttributeMaxDynamicSharedMemorySize, GEMM_SMEM);
    cudaFuncSetAttribute(gemm_fp16<float>,  cudaFuncAttributeMaxDynamicSharedMemorySize, GEMM_SMEM);

    // fused fp16 conversions (one launch for hs, w_in, w_out)
    {
        const long long n0 = (long long)MROWS * HID / 4;   // hs
        const long long n1 = (long long)CH * HID / 4;      // w_in
        const long long n2 = (long long)HID * CH / 4;      // w_out
        convert_fp16_fused<<<2368, 256>>>(hs, hs16, n0,
                                          w_in, win16, n1,
                                          w_out, wout16, n2);
    }

    // GEMM1: x = hs @ w_in^T + b_in   [16384, 4096]  (fp16 out)
    {
        dim3 grid(CH / 128, MROWS / 128);   // (32, 128)
        gemm_fp16<__half><<<grid, 256, GEMM_SMEM>>>(hs16, win16, b_in, xbuf,
                                                    MROWS, CH, HID);
    }

    // conv + SiLU -> y (fp16), 2 channels per thread
    {
        dim3 grid((CH / 2) / 256, SEQ / SCH, BATCH);  // (8, 64, 4)
        conv_silu<<<grid, 256>>>(xbuf, conv_w, conv_b, ybuf);
    }

    // GEMM2: out = y @ w_out^T + b_out  [16384, 2048]  (fp32 out)
    {
        dim3 grid(HID / 128, MROWS / 128);  // (16, 128)
        gemm_fp16<float><<<grid, 256, GEMM_SMEM>>>(ybuf, wout16, b_out, out,
                                                   MROWS, HID, CH);
    }
}

// round 15
// speedup vs baseline: 1.0302x; 1.0069x over previous
#include <cuda_runtime.h>
#include <cuda_fp16.h>
#include <cstdint>

// ---------------------------------------------------------------------------
// Problem dims
// ---------------------------------------------------------------------------
#define HID   2048
#define CH    4096
#define SEQ   4096
#define BATCH 4
#define MROWS (BATCH * SEQ)   // 16384

// ---------------------------------------------------------------------------
// Device scratch (allocation-free rule)
// ---------------------------------------------------------------------------
__device__ __half g_hs16  [(size_t)MROWS * HID];   // hs as fp16
__device__ __half g_win16 [(size_t)CH * HID];      // w_in as fp16
__device__ __half g_wout16[(size_t)HID * CH];      // w_out as fp16
__device__ __half g_x     [(size_t)MROWS * CH];    // after in-proj (fp16)
__device__ __half g_y     [(size_t)MROWS * CH];    // conv+silu (fp16)

// ---------------------------------------------------------------------------
// PTX helpers (arch-generic: cp.async / ldmatrix / mma.sync)
// ---------------------------------------------------------------------------
__device__ __forceinline__ uint32_t smem_u32(const void* p) {
    uint32_t a;
    asm("{ .reg .u64 t; cvta.to.shared.u64 t, %1; cvt.u32.u64 %0, t; }" : "=r"(a) : "l"(p));
    return a;
}
__device__ __forceinline__ void cp16(uint32_t dst, const void* src) {
    asm volatile("cp.async.cg.shared.global [%0], [%1], 16;" :: "r"(dst), "l"(src));
}
__device__ __forceinline__ void cp_commit() { asm volatile("cp.async.commit_group;" ::: "memory"); }
__device__ __forceinline__ void cp_wait2()  { asm volatile("cp.async.wait_group 2;"  ::: "memory"); }
__device__ __forceinline__ void cp_wait0()  { asm volatile("cp.async.wait_group 0;"  ::: "memory"); }

__device__ __forceinline__ void ldsm_x4(uint32_t* r, uint32_t addr) {
    asm volatile("ldmatrix.sync.aligned.m8n8.x4.shared.b16 {%0,%1,%2,%3}, [%4];"
        : "=r"(r[0]), "=r"(r[1]), "=r"(r[2]), "=r"(r[3]) : "r"(addr));
}
__device__ __forceinline__ void mma16816(float* c, const uint32_t* a, const uint32_t* b) {
    asm volatile(
        "mma.sync.aligned.m16n8k16.row.col.f32.f16.f16.f32 "
        "{%0,%1,%2,%3}, {%4,%5,%6,%7}, {%8,%9}, {%0,%1,%2,%3};"
        : "+f"(c[0]), "+f"(c[1]), "+f"(c[2]), "+f"(c[3])
        : "r"(a[0]), "r"(a[1]), "r"(a[2]), "r"(a[3]), "r"(b[0]), "r"(b[1]));
}

// ---------------------------------------------------------------------------
// GEMM: C[m,n] = sum_k A[m,k]*B[n,k] + bias[n]   (fp16 in, fp32 acc)
// CTA 128x128, 8 warps (warp tile 32x64), BK=64, 3 stages, occ 2.
// LDA=72 (144B rows) -> conflict-free ldsm.
// R12/R14-FROZEN SOURCE: this exact formulation measured 585-588us/GEMM,
// 77.8% tensor.  Three perturbations (R7, R10, R13) all regressed it.
// DO NOT REORDER OR REWRITE.
// ---------------------------------------------------------------------------
#define BK    64
#define LDA   72
#define MATB  (128 * LDA)                 // 9216 elems / tile
#define STAGE_ELEMS (2 * MATB)            // A, B
#define STAGES 3
#define GEMM_SMEM (STAGES * STAGE_ELEMS * 2)  // 110592 bytes

template <typename OutT>
__global__ void __launch_bounds__(256, 2)
gemm_fp16(const __half* __restrict__ A, const __half* __restrict__ B,
          const float* __restrict__ bias, OutT* __restrict__ C,
          int M, int N, int K)
{
    extern __shared__ __align__(16) char smraw[];
    const uint32_t sbase = smem_u32(smraw);

    const int tid  = threadIdx.x;
    const int wid  = tid >> 5;
    const int lane = tid & 31;
    const int bm   = blockIdx.y * 128;
    const int bn   = blockIdx.x * 128;
    const int wm   = (wid & 3) * 32;     // warp row offset
    const int wn   = (wid >> 2) * 64;    // warp col offset

    // precomputed per-warp ldsm byte offsets (vary only by +kk*32 in-loop)
    uint32_t aBase[2], bBase[4];
#pragma unroll
    for (int mt = 0; mt < 2; mt++)
        aBase[mt] = (uint32_t)((wm + mt * 16 + (lane & 15)) * LDA + (lane >> 4) * 8) * 2;
#pragma unroll
    for (int q = 0; q < 4; q++)
        bBase[q] = (uint32_t)((wn + q * 16 + (lane & 7) + ((lane >> 4) << 3)) * LDA
                              + ((lane >> 3) & 1) * 8) * 2;

    // loader offsets
    const int lrow = tid >> 3;
    const int lkc  = (tid & 7) * 8;
    const uint32_t lsoff = (uint32_t)(lrow * LDA + lkc) * 2;

    float acc[2][8][4];
#pragma unroll
    for (int i = 0; i < 2; i++)
#pragma unroll
        for (int j = 0; j < 8; j++)
#pragma unroll
            for (int k = 0; k < 4; k++) acc[i][j][k] = 0.0f;

    const int nchunks = K / BK;

    // half-stage loaders (A half / B half), each its own commit group
    auto load_A = [&](int slot, int k0) {
        const uint32_t st = sbase + (uint32_t)slot * STAGE_ELEMS * 2;
#pragma unroll
        for (int i = 0; i < 4; i++)
            cp16(st + lsoff + (uint32_t)(32 * i) * LDA * 2,
                 A + (size_t)(bm + lrow + 32 * i) * K + k0 + lkc);
        cp_commit();
    };
    auto load_B = [&](int slot, int k0) {
        const uint32_t st = sbase + (uint32_t)slot * STAGE_ELEMS * 2 + MATB * 2;
#pragma unroll
        for (int i = 0; i < 4; i++)
            cp16(st + lsoff + (uint32_t)(32 * i) * LDA * 2,
                 B + (size_t)(bn + lrow + 32 * i) * K + k0 + lkc);
        cp_commit();
    };

    auto do_kk = [&](uint32_t sA, uint32_t sB, int kk) {
        const uint32_t ko = (uint32_t)kk * 32;
        uint32_t a[2][4];
#pragma unroll
        for (int mt = 0; mt < 2; mt++) ldsm_x4(a[mt], sA + aBase[mt] + ko);
        uint32_t b[4][4];
#pragma unroll
        for (int q = 0; q < 4; q++)    ldsm_x4(b[q], sB + bBase[q] + ko);
#pragma unroll
        for (int mt = 0; mt < 2; mt++)
#pragma unroll
            for (int q = 0; q < 4; q++)
#pragma unroll
                for (int h = 0; h < 2; h++)
                    mma16816(acc[mt][q * 2 + h], a[mt], &b[q][h * 2]);
    };

    // prologue: 2 stages in flight (4 commit groups)
    load_A(0, 0);      load_B(0, 0);
    load_A(1, BK);     load_B(1, BK);

    for (int i = 0; i < nchunks; i++) {
        if (i + 1 < nchunks) cp_wait2(); else cp_wait0();
        __syncthreads();

        const uint32_t st = sbase + (uint32_t)(i % STAGES) * STAGE_ELEMS * 2;
        const uint32_t sA = st;
        const uint32_t sB = st + MATB * 2;
        const bool pf = (i + 2 < nchunks);
        const int  ps = (i + 2) % STAGES;
        const int  pk = (i + 2) * BK;

        do_kk(sA, sB, 0);
        if (pf) load_A(ps, pk);
        do_kk(sA, sB, 1);
        if (pf) load_B(ps, pk);
        do_kk(sA, sB, 2);
        do_kk(sA, sB, 3);
        // single barrier per iteration: slot (i+2)%3 was last read in iter
        // i-1, ordered by this iteration's __syncthreads.
    }

    // --- epilogue: fused bias ---
    const int r  = lane >> 2;
    const int cc = (lane & 3) * 2;
#pragma unroll
    for (int mt = 0; mt < 2; mt++) {
        const int row0 = bm + wm + mt * 16;
#pragma unroll
        for (int nt = 0; nt < 8; nt++) {
            const int col0 = bn + wn + nt * 8;
            const float2 bv = *reinterpret_cast<const float2*>(bias + col0 + cc);
            const float v00 = acc[mt][nt][0] + bv.x, v01 = acc[mt][nt][1] + bv.y;
            const float v10 = acc[mt][nt][2] + bv.x, v11 = acc[mt][nt][3] + bv.y;
            OutT* p0 = C + (size_t)(row0 + r) * N + col0 + cc;
            OutT* p1 = C + (size_t)(row0 + r + 8) * N + col0 + cc;
            if constexpr (sizeof(OutT) == 4) {
                float2 o0, o1;
                o0.x = v00; o0.y = v01; o1.x = v10; o1.y = v11;
                *reinterpret_cast<float2*>(p0) = o0;
                *reinterpret_cast<float2*>(p1) = o1;
            } else {
                __half2 o0, o1;
                o0.x = __float2half(v00); o0.y = __float2half(v01);
                o1.x = __float2half(v10); o1.y = __float2half(v11);
                *reinterpret_cast<__half2*>(p0) = o0;
                *reinterpret_cast<__half2*>(p1) = o1;
            }
        }
    }
}

// ---------------------------------------------------------------------------
// Fused fp32 -> fp16 convert over THREE arrays in one launch (grid-stride).
// ---------------------------------------------------------------------------
__global__ void __launch_bounds__(256)
convert_fp16_fused(const float* __restrict__ s0, __half* __restrict__ d0, long long n0,
                   const float* __restrict__ s1, __half* __restrict__ d1, long long n1,
                   const float* __restrict__ s2, __half* __restrict__ d2, long long n2)
{
    const long long total = n0 + n1 + n2;
    const long long stride = (long long)gridDim.x * blockDim.x;
    for (long long i = (long long)blockIdx.x * blockDim.x + threadIdx.x;
         i < total; i += stride) {
        const float* src; __half* dst; long long j;
        if (i < n0)           { src = s0; dst = d0; j = i; }
        else if (i < n0 + n1) { src = s1; dst = d1; j = i - n0; }
        else                  { src = s2; dst = d2; j = i - n0 - n1; }
        const float4 v = reinterpret_cast<const float4*>(src)[j];
        __half2 p0, p1;
        p0.x = __float2half(v.x); p0.y = __float2half(v.y);
        p1.x = __float2half(v.z); p1.y = __float2half(v.w);
        reinterpret_cast<__half2*>(dst)[2 * j]     = p0;
        reinterpret_cast<__half2*>(dst)[2 * j + 1] = p1;
    }
}

// ---------------------------------------------------------------------------
// Causal depthwise conv (K=4) + bias + SiLU, fp16 in -> fp16 out.
// Each thread handles TWO adjacent channels (half2) x SCH seq positions.
// SCH=32: 8192 blocks, short serial chains for latency hiding.
// ---------------------------------------------------------------------------
#define SCH 32
__global__ void __launch_bounds__(256)
conv_silu(const __half* __restrict__ x, const float* __restrict__ cw,
          const float* __restrict__ cb, __half* __restrict__ y)
{
    const int c2 = blockIdx.x * 256 + threadIdx.x;   // half2 channel index
    const int c  = c2 * 2;
    const int b  = blockIdx.z;
    const int s0 = blockIdx.y * SCH;

    const float4 wA = *reinterpret_cast<const float4*>(cw + (size_t)c * 4);
    const float4 wB = *reinterpret_cast<const float4*>(cw + (size_t)(c + 1) * 4);
    const float2 bias = *reinterpret_cast<const float2*>(cb + c);

    const __half2* xp = reinterpret_cast<const __half2*>(x) + c2;
    __half2*       yp = reinterpret_cast<__half2*>(y) + c2;
    const size_t CH2 = CH / 2;
    const size_t base = (size_t)b * SEQ * CH2;

    float2 m3, m2, m1;
    if (s0 == 0) { m3 = m2 = m1 = make_float2(0.f, 0.f); }
    else {
        m3 = __half22float2(xp[base + (size_t)(s0 - 3) * CH2]);
        m2 = __half22float2(xp[base + (size_t)(s0 - 2) * CH2]);
        m1 = __half22float2(xp[base + (size_t)(s0 - 1) * CH2]);
    }

#pragma unroll 8
    for (int s = s0; s < s0 + SCH; s++) {
        const float2 xc = __half22float2(xp[base + (size_t)s * CH2]);
        float a0 = bias.x, a1 = bias.y;
        a0 = fmaf(wA.x, m3.x, a0);  a1 = fmaf(wB.x, m3.y, a1);
        a0 = fmaf(wA.y, m2.x, a0);  a1 = fmaf(wB.y, m2.y, a1);
        a0 = fmaf(wA.z, m1.x, a0);  a1 = fmaf(wB.z, m1.y, a1);
        a0 = fmaf(wA.w, xc.x, a0);  a1 = fmaf(wB.w, xc.y, a1);
        const float v0 = a0 / (1.0f + __expf(-a0));
        const float v1 = a1 / (1.0f + __expf(-a1));
        __half2 o;
        o.x = __float2half(v0);
        o.y = __float2half(v1);
        yp[base + (size_t)s * CH2] = o;
        m3 = m2; m2 = m1; m1 = xc;
    }
}

// ---------------------------------------------------------------------------
// Launch: hidden_states, w_in, b_in, conv_w, conv_b, w_out, b_out
// ---------------------------------------------------------------------------
extern "C" void kernel_launch(void* const* d_in, const int* in_sizes, int n_in,
                              void* d_out, int out_size)
{
    const float* hs     = (const float*)d_in[0];
    const float* w_in   = (const float*)d_in[1];
    const float* b_in   = (const float*)d_in[2];
    const float* conv_w = (const float*)d_in[3];
    const float* conv_b = (const float*)d_in[4];
    const float* w_out  = (const float*)d_in[5];
    const float* b_out  = (const float*)d_in[6];
    float* out = (float*)d_out;

    __half *hs16, *win16, *wout16, *xbuf, *ybuf;
    cudaGetSymbolAddress((void**)&hs16,   g_hs16);
    cudaGetSymbolAddress((void**)&win16,  g_win16);
    cudaGetSymbolAddress((void**)&wout16, g_wout16);
    cudaGetSymbolAddress((void**)&xbuf,   g_x);
    cudaGetSymbolAddress((void**)&ybuf,   g_y);

    cudaFuncSetAttribute(gemm_fp16<__half>, cudaFuncAttributeMaxDynamicSharedMemorySize, GEMM_SMEM);
    cudaFuncSetAttribute(gemm_fp16<float>,  cudaFuncAttributeMaxDynamicSharedMemorySize, GEMM_SMEM);

    // fused fp16 conversions (one launch for hs, w_in, w_out)
    {
        const long long n0 = (long long)MROWS * HID / 4;   // hs
        const long long n1 = (long long)CH * HID / 4;      // w_in
        const long long n2 = (long long)HID * CH / 4;      // w_out
        convert_fp16_fused<<<4736, 256>>>(hs, hs16, n0,
                                          w_in, win16, n1,
                                          w_out, wout16, n2);
    }

    // GEMM1: x = hs @ w_in^T + b_in   [16384, 4096]  (fp16 out)
    {
        dim3 grid(CH / 128, MROWS / 128);   // (32, 128)
        gemm_fp16<__half><<<grid, 256, GEMM_SMEM>>>(hs16, win16, b_in, xbuf,
                                                    MROWS, CH, HID);
    }

    // conv + SiLU -> y (fp16), 2 channels per thread
    {
        dim3 grid((CH / 2) / 256, SEQ / SCH, BATCH);  // (8, 128, 4)
        conv_silu<<<grid, 256>>>(xbuf, conv_w, conv_b, ybuf);
    }

    // GEMM2: out = y @ w_out^T + b_out  [16384, 2048]  (fp32 out)
    {
        dim3 grid(HID / 128, MROWS / 128);  // (16, 128)
        gemm_fp16<float><<<grid, 256, GEMM_SMEM>>>(ybuf, wout16, b_out, out,
                                                   MROWS, HID, CH);
    }
}

// round 16
// speedup vs baseline: 1.0362x; 1.0058x over previous
#include <cuda_runtime.h>
#include <cuda_fp16.h>
#include <cstdint>

// ---------------------------------------------------------------------------
// Problem dims
// ---------------------------------------------------------------------------
#define HID   2048
#define CH    4096
#define SEQ   4096
#define BATCH 4
#define MROWS (BATCH * SEQ)   // 16384

// ---------------------------------------------------------------------------
// Device scratch (allocation-free rule)
// ---------------------------------------------------------------------------
__device__ __half g_hs16  [(size_t)MROWS * HID];   // hs as fp16
__device__ __half g_win16 [(size_t)CH * HID];      // w_in as fp16
__device__ __half g_wout16[(size_t)HID * CH];      // w_out as fp16
__device__ __half g_x     [(size_t)MROWS * CH];    // after in-proj (fp16)
__device__ __half g_y     [(size_t)MROWS * CH];    // conv+silu (fp16)

// ---------------------------------------------------------------------------
// PTX helpers (arch-generic: cp.async / ldmatrix / mma.sync)
// ---------------------------------------------------------------------------
__device__ __forceinline__ uint32_t smem_u32(const void* p) {
    uint32_t a;
    asm("{ .reg .u64 t; cvta.to.shared.u64 t, %1; cvt.u32.u64 %0, t; }" : "=r"(a) : "l"(p));
    return a;
}
__device__ __forceinline__ void cp16(uint32_t dst, const void* src) {
    asm volatile("cp.async.cg.shared.global [%0], [%1], 16;" :: "r"(dst), "l"(src));
}
__device__ __forceinline__ void cp_commit() { asm volatile("cp.async.commit_group;" ::: "memory"); }
__device__ __forceinline__ void cp_wait2()  { asm volatile("cp.async.wait_group 2;"  ::: "memory"); }
__device__ __forceinline__ void cp_wait0()  { asm volatile("cp.async.wait_group 0;"  ::: "memory"); }

__device__ __forceinline__ void ldsm_x4(uint32_t* r, uint32_t addr) {
    asm volatile("ldmatrix.sync.aligned.m8n8.x4.shared.b16 {%0,%1,%2,%3}, [%4];"
        : "=r"(r[0]), "=r"(r[1]), "=r"(r[2]), "=r"(r[3]) : "r"(addr));
}
__device__ __forceinline__ void mma16816(float* c, const uint32_t* a, const uint32_t* b) {
    asm volatile(
        "mma.sync.aligned.m16n8k16.row.col.f32.f16.f16.f32 "
        "{%0,%1,%2,%3}, {%4,%5,%6,%7}, {%8,%9}, {%0,%1,%2,%3};"
        : "+f"(c[0]), "+f"(c[1]), "+f"(c[2]), "+f"(c[3])
        : "r"(a[0]), "r"(a[1]), "r"(a[2]), "r"(a[3]), "r"(b[0]), "r"(b[1]));
}

// ---------------------------------------------------------------------------
// GEMM: C[m,n] = sum_k A[m,k]*B[n,k] + bias[n]   (fp16 in, fp32 acc)
// CTA 128x128, 8 warps (warp tile 32x64), BK=64, 3 stages, occ 2.
// LDA=72 (144B rows) -> conflict-free ldsm.
// R12/R14/R15-FROZEN SOURCE: 585-590us/GEMM, 77.8% tensor.  Three
// perturbations (R7, R10, R13) all regressed it.  DO NOT TOUCH.
// ---------------------------------------------------------------------------
#define BK    64
#define LDA   72
#define MATB  (128 * LDA)                 // 9216 elems / tile
#define STAGE_ELEMS (2 * MATB)            // A, B
#define STAGES 3
#define GEMM_SMEM (STAGES * STAGE_ELEMS * 2)  // 110592 bytes

template <typename OutT>
__global__ void __launch_bounds__(256, 2)
gemm_fp16(const __half* __restrict__ A, const __half* __restrict__ B,
          const float* __restrict__ bias, OutT* __restrict__ C,
          int M, int N, int K)
{
    extern __shared__ __align__(16) char smraw[];
    const uint32_t sbase = smem_u32(smraw);

    const int tid  = threadIdx.x;
    const int wid  = tid >> 5;
    const int lane = tid & 31;
    const int bm   = blockIdx.y * 128;
    const int bn   = blockIdx.x * 128;
    const int wm   = (wid & 3) * 32;     // warp row offset
    const int wn   = (wid >> 2) * 64;    // warp col offset

    // precomputed per-warp ldsm byte offsets (vary only by +kk*32 in-loop)
    uint32_t aBase[2], bBase[4];
#pragma unroll
    for (int mt = 0; mt < 2; mt++)
        aBase[mt] = (uint32_t)((wm + mt * 16 + (lane & 15)) * LDA + (lane >> 4) * 8) * 2;
#pragma unroll
    for (int q = 0; q < 4; q++)
        bBase[q] = (uint32_t)((wn + q * 16 + (lane & 7) + ((lane >> 4) << 3)) * LDA
                              + ((lane >> 3) & 1) * 8) * 2;

    // loader offsets
    const int lrow = tid >> 3;
    const int lkc  = (tid & 7) * 8;
    const uint32_t lsoff = (uint32_t)(lrow * LDA + lkc) * 2;

    float acc[2][8][4];
#pragma unroll
    for (int i = 0; i < 2; i++)
#pragma unroll
        for (int j = 0; j < 8; j++)
#pragma unroll
            for (int k = 0; k < 4; k++) acc[i][j][k] = 0.0f;

    const int nchunks = K / BK;

    // half-stage loaders (A half / B half), each its own commit group
    auto load_A = [&](int slot, int k0) {
        const uint32_t st = sbase + (uint32_t)slot * STAGE_ELEMS * 2;
#pragma unroll
        for (int i = 0; i < 4; i++)
            cp16(st + lsoff + (uint32_t)(32 * i) * LDA * 2,
                 A + (size_t)(bm + lrow + 32 * i) * K + k0 + lkc);
        cp_commit();
    };
    auto load_B = [&](int slot, int k0) {
        const uint32_t st = sbase + (uint32_t)slot * STAGE_ELEMS * 2 + MATB * 2;
#pragma unroll
        for (int i = 0; i < 4; i++)
            cp16(st + lsoff + (uint32_t)(32 * i) * LDA * 2,
                 B + (size_t)(bn + lrow + 32 * i) * K + k0 + lkc);
        cp_commit();
    };

    auto do_kk = [&](uint32_t sA, uint32_t sB, int kk) {
        const uint32_t ko = (uint32_t)kk * 32;
        uint32_t a[2][4];
#pragma unroll
        for (int mt = 0; mt < 2; mt++) ldsm_x4(a[mt], sA + aBase[mt] + ko);
        uint32_t b[4][4];
#pragma unroll
        for (int q = 0; q < 4; q++)    ldsm_x4(b[q], sB + bBase[q] + ko);
#pragma unroll
        for (int mt = 0; mt < 2; mt++)
#pragma unroll
            for (int q = 0; q < 4; q++)
#pragma unroll
                for (int h = 0; h < 2; h++)
                    mma16816(acc[mt][q * 2 + h], a[mt], &b[q][h * 2]);
    };

    // prologue: 2 stages in flight (4 commit groups)
    load_A(0, 0);      load_B(0, 0);
    load_A(1, BK);     load_B(1, BK);

    for (int i = 0; i < nchunks; i++) {
        if (i + 1 < nchunks) cp_wait2(); else cp_wait0();
        __syncthreads();

        const uint32_t st = sbase + (uint32_t)(i % STAGES) * STAGE_ELEMS * 2;
        const uint32_t sA = st;
        const uint32_t sB = st + MATB * 2;
        const bool pf = (i + 2 < nchunks);
        const int  ps = (i + 2) % STAGES;
        const int  pk = (i + 2) * BK;

        do_kk(sA, sB, 0);
        if (pf) load_A(ps, pk);
        do_kk(sA, sB, 1);
        if (pf) load_B(ps, pk);
        do_kk(sA, sB, 2);
        do_kk(sA, sB, 3);
        // single barrier per iteration: slot (i+2)%3 was last read in iter
        // i-1, ordered by this iteration's __syncthreads.
    }

    // --- epilogue: fused bias ---
    const int r  = lane >> 2;
    const int cc = (lane & 3) * 2;
#pragma unroll
    for (int mt = 0; mt < 2; mt++) {
        const int row0 = bm + wm + mt * 16;
#pragma unroll
        for (int nt = 0; nt < 8; nt++) {
            const int col0 = bn + wn + nt * 8;
            const float2 bv = *reinterpret_cast<const float2*>(bias + col0 + cc);
            const float v00 = acc[mt][nt][0] + bv.x, v01 = acc[mt][nt][1] + bv.y;
            const float v10 = acc[mt][nt][2] + bv.x, v11 = acc[mt][nt][3] + bv.y;
            OutT* p0 = C + (size_t)(row0 + r) * N + col0 + cc;
            OutT* p1 = C + (size_t)(row0 + r + 8) * N + col0 + cc;
            if constexpr (sizeof(OutT) == 4) {
                float2 o0, o1;
                o0.x = v00; o0.y = v01; o1.x = v10; o1.y = v11;
                *reinterpret_cast<float2*>(p0) = o0;
                *reinterpret_cast<float2*>(p1) = o1;
            } else {
                __half2 o0, o1;
                o0.x = __float2half(v00); o0.y = __float2half(v01);
                o1.x = __float2half(v10); o1.y = __float2half(v11);
                *reinterpret_cast<__half2*>(p0) = o0;
                *reinterpret_cast<__half2*>(p1) = o1;
            }
        }
    }
}

// ---------------------------------------------------------------------------
// Fused fp32 -> fp16 convert over THREE arrays in one launch (grid-stride).
// ---------------------------------------------------------------------------
__global__ void __launch_bounds__(256)
convert_fp16_fused(const float* __restrict__ s0, __half* __restrict__ d0, long long n0,
                   const float* __restrict__ s1, __half* __restrict__ d1, long long n1,
                   const float* __restrict__ s2, __half* __restrict__ d2, long long n2)
{
    const long long total = n0 + n1 + n2;
    const long long stride = (long long)gridDim.x * blockDim.x;
    for (long long i = (long long)blockIdx.x * blockDim.x + threadIdx.x;
         i < total; i += stride) {
        const float* src; __half* dst; long long j;
        if (i < n0)           { src = s0; dst = d0; j = i; }
        else if (i < n0 + n1) { src = s1; dst = d1; j = i - n0; }
        else                  { src = s2; dst = d2; j = i - n0 - n1; }
        const float4 v = reinterpret_cast<const float4*>(src)[j];
        __half2 p0, p1;
        p0.x = __float2half(v.x); p0.y = __float2half(v.y);
        p1.x = __float2half(v.z); p1.y = __float2half(v.w);
        reinterpret_cast<__half2*>(dst)[2 * j]     = p0;
        reinterpret_cast<__half2*>(dst)[2 * j + 1] = p1;
    }
}

// ---------------------------------------------------------------------------
// Causal depthwise conv (K=4) + bias + SiLU, fp16 in -> fp16 out.
// Each thread handles FOUR adjacent channels (uint2 = 2 x half2) per seq
// step: 8-byte loads/stores halve LSU instruction count vs half2.
// SCH=32: 2048 blocks (4,128,4), short serial chains.
// ---------------------------------------------------------------------------
#define SCH 32
__global__ void __launch_bounds__(256)
conv_silu(const __half* __restrict__ x, const float* __restrict__ cw,
          const float* __restrict__ cb, __half* __restrict__ y)
{
    const int c4 = blockIdx.x * 256 + threadIdx.x;   // 4-channel group index
    const int c  = c4 * 4;
    const int b  = blockIdx.z;
    const int s0 = blockIdx.y * SCH;

    // per-channel taps: w[j][k] for j=0..3 channels
    const float4 w0 = *reinterpret_cast<const float4*>(cw + (size_t)(c + 0) * 4);
    const float4 w1 = *reinterpret_cast<const float4*>(cw + (size_t)(c + 1) * 4);
    const float4 w2 = *reinterpret_cast<const float4*>(cw + (size_t)(c + 2) * 4);
    const float4 w3 = *reinterpret_cast<const float4*>(cw + (size_t)(c + 3) * 4);
    const float4 bias = *reinterpret_cast<const float4*>(cb + c);

    const uint2* xp = reinterpret_cast<const uint2*>(x) + c4;
    uint2*       yp = reinterpret_cast<uint2*>(y) + c4;
    const size_t CH4 = CH / 4;
    const size_t base = (size_t)b * SEQ * CH4;

    auto unpack = [](uint2 u, float* f) {
        const __half2 h0 = *reinterpret_cast<const __half2*>(&u.x);
        const __half2 h1 = *reinterpret_cast<const __half2*>(&u.y);
        const float2 f0 = __half22float2(h0);
        const float2 f1 = __half22float2(h1);
        f[0] = f0.x; f[1] = f0.y; f[2] = f1.x; f[3] = f1.y;
    };

    float m3[4], m2[4], m1[4];
    if (s0 == 0) {
#pragma unroll
        for (int j = 0; j < 4; j++) { m3[j] = m2[j] = m1[j] = 0.0f; }
    } else {
        unpack(xp[base + (size_t)(s0 - 3) * CH4], m3);
        unpack(xp[base + (size_t)(s0 - 2) * CH4], m2);
        unpack(xp[base + (size_t)(s0 - 1) * CH4], m1);
    }

#pragma unroll 4
    for (int s = s0; s < s0 + SCH; s++) {
        float xc[4];
        unpack(xp[base + (size_t)s * CH4], xc);

        float a0 = bias.x, a1 = bias.y, a2 = bias.z, a3 = bias.w;
        a0 = fmaf(w0.x, m3[0], a0); a1 = fmaf(w1.x, m3[1], a1);
        a2 = fmaf(w2.x, m3[2], a2); a3 = fmaf(w3.x, m3[3], a3);
        a0 = fmaf(w0.y, m2[0], a0); a1 = fmaf(w1.y, m2[1], a1);
        a2 = fmaf(w2.y, m2[2], a2); a3 = fmaf(w3.y, m2[3], a3);
        a0 = fmaf(w0.z, m1[0], a0); a1 = fmaf(w1.z, m1[1], a1);
        a2 = fmaf(w2.z, m1[2], a2); a3 = fmaf(w3.z, m1[3], a3);
        a0 = fmaf(w0.w, xc[0], a0); a1 = fmaf(w1.w, xc[1], a1);
        a2 = fmaf(w2.w, xc[2], a2); a3 = fmaf(w3.w, xc[3], a3);

        const float v0 = a0 / (1.0f + __expf(-a0));
        const float v1 = a1 / (1.0f + __expf(-a1));
        const float v2 = a2 / (1.0f + __expf(-a2));
        const float v3 = a3 / (1.0f + __expf(-a3));

        __half2 o0, o1;
        o0.x = __float2half(v0); o0.y = __float2half(v1);
        o1.x = __float2half(v2); o1.y = __float2half(v3);
        uint2 ov;
        ov.x = *reinterpret_cast<uint32_t*>(&o0);
        ov.y = *reinterpret_cast<uint32_t*>(&o1);
        yp[base + (size_t)s * CH4] = ov;

#pragma unroll
        for (int j = 0; j < 4; j++) { m3[j] = m2[j]; m2[j] = m1[j]; m1[j] = xc[j]; }
    }
}

// ---------------------------------------------------------------------------
// Launch: hidden_states, w_in, b_in, conv_w, conv_b, w_out, b_out
// ---------------------------------------------------------------------------
extern "C" void kernel_launch(void* const* d_in, const int* in_sizes, int n_in,
                              void* d_out, int out_size)
{
    const float* hs     = (const float*)d_in[0];
    const float* w_in   = (const float*)d_in[1];
    const float* b_in   = (const float*)d_in[2];
    const float* conv_w = (const float*)d_in[3];
    const float* conv_b = (const float*)d_in[4];
    const float* w_out  = (const float*)d_in[5];
    const float* b_out  = (const float*)d_in[6];
    float* out = (float*)d_out;

    __half *hs16, *win16, *wout16, *xbuf, *ybuf;
    cudaGetSymbolAddress((void**)&hs16,   g_hs16);
    cudaGetSymbolAddress((void**)&win16,  g_win16);
    cudaGetSymbolAddress((void**)&wout16, g_wout16);
    cudaGetSymbolAddress((void**)&xbuf,   g_x);
    cudaGetSymbolAddress((void**)&ybuf,   g_y);

    cudaFuncSetAttribute(gemm_fp16<__half>, cudaFuncAttributeMaxDynamicSharedMemorySize, GEMM_SMEM);
    cudaFuncSetAttribute(gemm_fp16<float>,  cudaFuncAttributeMaxDynamicSharedMemorySize, GEMM_SMEM);

    // fused fp16 conversions (one launch for hs, w_in, w_out)
    {
        const long long n0 = (long long)MROWS * HID / 4;   // hs
        const long long n1 = (long long)CH * HID / 4;      // w_in
        const long long n2 = (long long)HID * CH / 4;      // w_out
        convert_fp16_fused<<<4736, 256>>>(hs, hs16, n0,
                                          w_in, win16, n1,
                                          w_out, wout16, n2);
    }

    // GEMM1: x = hs @ w_in^T + b_in   [16384, 4096]  (fp16 out)
    {
        dim3 grid(CH / 128, MROWS / 128);   // (32, 128)
        gemm_fp16<__half><<<grid, 256, GEMM_SMEM>>>(hs16, win16, b_in, xbuf,
                                                    MROWS, CH, HID);
    }

    // conv + SiLU -> y (fp16), 4 channels per thread
    {
        dim3 grid((CH / 4) / 256, SEQ / SCH, BATCH);  // (4, 128, 4)
        conv_silu<<<grid, 256>>>(xbuf, conv_w, conv_b, ybuf);
    }

    // GEMM2: out = y @ w_out^T + b_out  [16384, 2048]  (fp32 out)
    {
        dim3 grid(HID / 128, MROWS / 128);  // (16, 128)
        gemm_fp16<float><<<grid, 256, GEMM_SMEM>>>(ybuf, wout16, b_out, out,
                                                   MROWS, HID, CH);
    }
}